// round 2
// baseline (speedup 1.0000x reference)
#include <cuda_runtime.h>
#include <cuda_bf16.h>

static constexpr int N = 50000;
static constexpr int E = 1600000;

// ---------------- scratch ----------------------------------------------------
__device__ __align__(16) float g_h0[N * 128];
__device__ __align__(16) float g_h1[N * 128];
__device__ __align__(16) __nv_bfloat16 g_bA[N * 128];
__device__ __align__(16) __nv_bfloat16 g_bB[N * 128];
__device__ __align__(16) float g_Wd0[2 * 256 * 128];   // duplicated weights (w,w)
__device__ __align__(16) float g_Wd1[2 * 256 * 128];
__device__ __align__(16) float g_Wd2[2 * 256 * 64];
__device__ int   g_deg[N];
__device__ int   g_row[N + 1];
__device__ int   g_fill[N];
__device__ int   g_csr[E];
__device__ float g_inv[N];

// ---------------- packed f32x2 FMA -------------------------------------------
__device__ __forceinline__ void ffma2(unsigned long long& a,
                                      unsigned long long x,
                                      unsigned long long y) {
    asm("fma.rn.f32x2 %0, %1, %2, %0;" : "+l"(a) : "l"(x), "l"(y));
}

// ---------------- CSR build --------------------------------------------------
__global__ void zero_deg_k() {
    int i = blockIdx.x * blockDim.x + threadIdx.x;
    if (i < N) g_deg[i] = 0;
}

__global__ void count_k(const int* __restrict__ dst) {
    int i = blockIdx.x * blockDim.x + threadIdx.x;
    if (i < E) atomicAdd(&g_deg[dst[i]], 1);
}

__global__ void scan_k() {
    __shared__ int wsum[32];
    __shared__ int carry;
    int tid = threadIdx.x, lane = tid & 31, wid = tid >> 5;
    if (tid == 0) carry = 0;
    __syncthreads();
    for (int base = 0; base < N; base += 1024) {
        int i = base + tid;
        int v = (i < N) ? g_deg[i] : 0;
        int x = v;
        #pragma unroll
        for (int o = 1; o < 32; o <<= 1) {
            int t = __shfl_up_sync(0xffffffffu, x, o);
            if (lane >= o) x += t;
        }
        if (lane == 31) wsum[wid] = x;
        __syncthreads();
        if (wid == 0) {
            int s = wsum[lane];
            #pragma unroll
            for (int o = 1; o < 32; o <<= 1) {
                int t = __shfl_up_sync(0xffffffffu, s, o);
                if (lane >= o) s += t;
            }
            wsum[lane] = s;
        }
        __syncthreads();
        int excl = x - v + (wid ? wsum[wid - 1] : 0) + carry;
        if (i < N) {
            g_row[i]  = excl;
            g_fill[i] = excl;
            g_inv[i]  = 1.0f / (float)(v > 0 ? v : 1);
        }
        __syncthreads();
        if (tid == 0) carry += wsum[31];
        __syncthreads();
    }
    if (tid == 0) g_row[N] = carry;
}

__global__ void scatter_k(const int* __restrict__ src, const int* __restrict__ dst) {
    int i = blockIdx.x * blockDim.x + threadIdx.x;
    if (i < E) {
        int pos = atomicAdd(&g_fill[dst[i]], 1);
        g_csr[pos] = src[i];
    }
}

// ---------------- prep: bf16 feature copy + duplicated weights ---------------
__global__ void prep_feat_k(const float* __restrict__ f) {
    int i = blockIdx.x * blockDim.x + threadIdx.x;
    if (i < N * 64) {
        float2 v = ((const float2*)f)[i];
        ((__nv_bfloat162*)g_bA)[i] = __float22bfloat162_rn(v);
    }
}

__global__ void dup_w_k(const float* __restrict__ W, int wsel, int n) {
    float* Wd = (wsel == 0) ? g_Wd0 : (wsel == 1 ? g_Wd1 : g_Wd2);
    int i = blockIdx.x * blockDim.x + threadIdx.x;
    if (i < n) {
        float w = W[i];
        Wd[2 * i]     = w;
        Wd[2 * i + 1] = w;
    }
}

// ---------------- fused SAGE layer -------------------------------------------
// Block = 256 thr = 8 warps. Warp owns 8 nodes.
// Phase 1: mean-aggregate (bf16 gather + fp32 self), write TRANSPOSED concat
//          into smem: smt[k][node] (k = 0..255, node col = 0..63, pad to 66).
// Phase 2: packed-f32x2 GEMM: node-pairs packed in the f32x2 lanes, weights
//          pre-duplicated in g_Wd* so no register packing is needed.
template <int FOUT, bool RELU>
__global__ void __launch_bounds__(256)
sage_k(const float* __restrict__ feat,
       float* __restrict__ dout,
       const float* __restrict__ bias,
       int self_sel, int gat_sel, int out_sel, int wsel) {
    constexpr int JP = FOUT / 32;           // outputs per lane (4 or 2)
    extern __shared__ float smt[];          // [256][66]

    const float* hs = (self_sel == 0) ? feat : (self_sel == 1 ? g_h0 : g_h1);
    const __nv_bfloat16* hg = (gat_sel == 0) ? g_bA : g_bB;
    float* of = (out_sel == 0) ? dout : (out_sel == 1 ? g_h0 : g_h1);
    __nv_bfloat16* ob = (out_sel == 1) ? g_bB : g_bA;   // only used if FOUT==128
    const float* Wd = (wsel == 0) ? g_Wd0 : (wsel == 1 ? g_Wd1 : g_Wd2);

    int tid = threadIdx.x, lane = tid & 31, w = tid >> 5;
    int node0 = blockIdx.x * 64 + w * 8;
    int k4 = lane * 4;                       // this lane's 4 feature rows

    // ---- phase 1: aggregation ----
    #pragma unroll
    for (int j = 0; j < 8; j++) {
        int node = node0 + j;
        float4 acc  = make_float4(0.f, 0.f, 0.f, 0.f);
        float4 self = make_float4(0.f, 0.f, 0.f, 0.f);
        if (node < N) {
            int beg = g_row[node], end = g_row[node + 1];
            int e = beg;
            for (; e + 4 <= end; e += 4) {
                int s0 = g_csr[e + 0], s1 = g_csr[e + 1];
                int s2 = g_csr[e + 2], s3 = g_csr[e + 3];
                uint2 r0 = *(const uint2*)(hg + s0 * 128 + k4);
                uint2 r1 = *(const uint2*)(hg + s1 * 128 + k4);
                uint2 r2 = *(const uint2*)(hg + s2 * 128 + k4);
                uint2 r3 = *(const uint2*)(hg + s3 * 128 + k4);
                acc.x += (__uint_as_float(r0.x << 16) + __uint_as_float(r1.x << 16))
                       + (__uint_as_float(r2.x << 16) + __uint_as_float(r3.x << 16));
                acc.y += (__uint_as_float(r0.x & 0xffff0000u) + __uint_as_float(r1.x & 0xffff0000u))
                       + (__uint_as_float(r2.x & 0xffff0000u) + __uint_as_float(r3.x & 0xffff0000u));
                acc.z += (__uint_as_float(r0.y << 16) + __uint_as_float(r1.y << 16))
                       + (__uint_as_float(r2.y << 16) + __uint_as_float(r3.y << 16));
                acc.w += (__uint_as_float(r0.y & 0xffff0000u) + __uint_as_float(r1.y & 0xffff0000u))
                       + (__uint_as_float(r2.y & 0xffff0000u) + __uint_as_float(r3.y & 0xffff0000u));
            }
            for (; e < end; ++e) {
                int s = g_csr[e];
                uint2 r = *(const uint2*)(hg + s * 128 + k4);
                acc.x += __uint_as_float(r.x << 16);
                acc.y += __uint_as_float(r.x & 0xffff0000u);
                acc.z += __uint_as_float(r.y << 16);
                acc.w += __uint_as_float(r.y & 0xffff0000u);
            }
            float idg = g_inv[node];
            acc.x *= idg; acc.y *= idg; acc.z *= idg; acc.w *= idg;
            self = *(const float4*)(hs + node * 128 + k4);
        }
        int nc = w * 8 + j;
        smt[(k4 + 0) * 66 + nc] = self.x;
        smt[(k4 + 1) * 66 + nc] = self.y;
        smt[(k4 + 2) * 66 + nc] = self.z;
        smt[(k4 + 3) * 66 + nc] = self.w;
        smt[(128 + k4 + 0) * 66 + nc] = acc.x;
        smt[(128 + k4 + 1) * 66 + nc] = acc.y;
        smt[(128 + k4 + 2) * 66 + nc] = acc.z;
        smt[(128 + k4 + 3) * 66 + nc] = acc.w;
    }
    __syncwarp();   // warp reads only its own 8 smem columns

    // ---- phase 2: packed-f32x2 GEMM ----
    unsigned long long a[4][JP];            // [node-pair][output]
    #pragma unroll
    for (int jp = 0; jp < 4; jp++)
        #pragma unroll
        for (int i = 0; i < JP; i++) a[jp][i] = 0ull;

    const ulonglong2* W2 = (const ulonglong2*)Wd;   // row = FOUT/2 ulonglong2

    #pragma unroll 2
    for (int k = 0; k < 256; k++) {
        const float* hrow = &smt[k * 66 + w * 8];
        unsigned long long h0 = *(const unsigned long long*)(hrow + 0);
        unsigned long long h1 = *(const unsigned long long*)(hrow + 2);
        unsigned long long h2 = *(const unsigned long long*)(hrow + 4);
        unsigned long long h3 = *(const unsigned long long*)(hrow + 6);
        if constexpr (JP == 4) {
            ulonglong2 wa = W2[k * (FOUT / 2) + lane * 2];
            ulonglong2 wb = W2[k * (FOUT / 2) + lane * 2 + 1];
            ffma2(a[0][0], h0, wa.x); ffma2(a[0][1], h0, wa.y);
            ffma2(a[0][2], h0, wb.x); ffma2(a[0][3], h0, wb.y);
            ffma2(a[1][0], h1, wa.x); ffma2(a[1][1], h1, wa.y);
            ffma2(a[1][2], h1, wb.x); ffma2(a[1][3], h1, wb.y);
            ffma2(a[2][0], h2, wa.x); ffma2(a[2][1], h2, wa.y);
            ffma2(a[2][2], h2, wb.x); ffma2(a[2][3], h2, wb.y);
            ffma2(a[3][0], h3, wa.x); ffma2(a[3][1], h3, wa.y);
            ffma2(a[3][2], h3, wb.x); ffma2(a[3][3], h3, wb.y);
        } else {
            ulonglong2 wa = W2[k * (FOUT / 2) + lane];
            ffma2(a[0][0], h0, wa.x); ffma2(a[0][1], h0, wa.y);
            ffma2(a[1][0], h1, wa.x); ffma2(a[1][1], h1, wa.y);
            ffma2(a[2][0], h2, wa.x); ffma2(a[2][1], h2, wa.y);
            ffma2(a[3][0], h3, wa.x); ffma2(a[3][1], h3, wa.y);
        }
    }

    // ---- epilogue: bias + relu + store (fp32 always, bf16 shadow if hidden) --
    float bb[JP];
    #pragma unroll
    for (int i = 0; i < JP; i++) bb[i] = __ldg(bias + lane * JP + i);

    #pragma unroll
    for (int jp = 0; jp < 4; jp++) {
        float2 v[JP];
        #pragma unroll
        for (int i = 0; i < JP; i++) v[i] = *reinterpret_cast<float2*>(&a[jp][i]);
        #pragma unroll
        for (int half = 0; half < 2; half++) {
            int node = node0 + jp * 2 + half;
            if (node >= N) continue;
            float o[JP];
            #pragma unroll
            for (int i = 0; i < JP; i++) {
                o[i] = (half ? v[i].y : v[i].x) + bb[i];
                if (RELU) o[i] = fmaxf(o[i], 0.f);
            }
            if constexpr (JP == 4) {
                *(float4*)(of + node * 128 + lane * 4) =
                    make_float4(o[0], o[1], o[2], o[3]);
                __nv_bfloat162 p0 = __float22bfloat162_rn(make_float2(o[0], o[1]));
                __nv_bfloat162 p1 = __float22bfloat162_rn(make_float2(o[2], o[3]));
                uint2 u;
                *(__nv_bfloat162*)&u.x = p0;
                *(__nv_bfloat162*)&u.y = p1;
                *(uint2*)(ob + node * 128 + lane * 4) = u;
            } else {
                *(float2*)(of + node * 64 + lane * 2) = make_float2(o[0], o[1]);
            }
        }
    }
}

// ---------------- launcher ----------------------------------------------------
extern "C" void kernel_launch(void* const* d_in, const int* in_sizes, int n_in,
                              void* d_out, int out_size) {
    const float* feat = (const float*)d_in[0];
    const int*   src  = (const int*)d_in[1];
    const int*   dst  = (const int*)d_in[2];
    const float* W0   = (const float*)d_in[3];
    const float* b0   = (const float*)d_in[4];
    const float* W1   = (const float*)d_in[5];
    const float* b1   = (const float*)d_in[6];
    const float* W2   = (const float*)d_in[7];
    const float* b2   = (const float*)d_in[8];
    float* out = (float*)d_out;

    const int SMEM = 256 * 66 * 4;   // 67584 B
    cudaFuncSetAttribute(sage_k<128, true >, cudaFuncAttributeMaxDynamicSharedMemorySize, SMEM);
    cudaFuncSetAttribute(sage_k< 64, false>, cudaFuncAttributeMaxDynamicSharedMemorySize, SMEM);

    const int TB = 256;
    zero_deg_k<<<(N + TB - 1) / TB, TB>>>();
    count_k<<<(E + TB - 1) / TB, TB>>>(dst);
    scan_k<<<1, 1024>>>();
    scatter_k<<<(E + TB - 1) / TB, TB>>>(src, dst);

    prep_feat_k<<<(N * 64 + TB - 1) / TB, TB>>>(feat);
    dup_w_k<<<(256 * 128 + TB - 1) / TB, TB>>>(W0, 0, 256 * 128);
    dup_w_k<<<(256 * 128 + TB - 1) / TB, TB>>>(W1, 1, 256 * 128);
    dup_w_k<<<(256 * 64 + TB - 1) / TB, TB>>>(W2, 2, 256 * 64);

    int lblocks = (N + 63) / 64;     // 782
    //                 feat  out  bias  self gat  out  w
    sage_k<128, true ><<<lblocks, TB, SMEM>>>(feat, out, b0, 0, 0, 1, 0);
    sage_k<128, true ><<<lblocks, TB, SMEM>>>(feat, out, b1, 1, 1, 2, 1);
    sage_k< 64, false><<<lblocks, TB, SMEM>>>(feat, out, b2, 2, 0, 0, 2);
}

// round 5
// speedup vs baseline: 2.1079x; 2.1079x over previous
#include <cuda_runtime.h>
#include <cstdint>

static constexpr int N = 50000;
static constexpr int E = 1600000;

// ---------------- scratch -----------------------------------------------------
__device__ __align__(16) float g_h0[N * 128];
__device__ __align__(16) float g_h1[N * 128];
__device__ __align__(16) float g_mean[N * 128];
__device__ __align__(16) float g_Wr0[256 * 128];   // tf32-rounded, [k][n]
__device__ __align__(16) float g_Wr1[256 * 128];
__device__ __align__(16) float g_Wr2[256 * 64];
__device__ int   g_deg[N];
__device__ int   g_row[N + 1];
__device__ int   g_fill[N];
__device__ int   g_csr[E];
__device__ float g_inv[N];

// cvt.rna.tf32.f32 needs a .b32 destination -> go through a uint register.
__device__ __forceinline__ float to_tf32(float x) {
    uint32_t u;
    asm("cvt.rna.tf32.f32 %0, %1;" : "=r"(u) : "f"(x));
    return __uint_as_float(u);
}

// ---------------- CSR build ---------------------------------------------------
__global__ void zero_deg_k() {
    int i = blockIdx.x * blockDim.x + threadIdx.x;
    if (i < N) g_deg[i] = 0;
}
__global__ void count_k(const int* __restrict__ dst) {
    int i = blockIdx.x * blockDim.x + threadIdx.x;
    if (i < E) atomicAdd(&g_deg[dst[i]], 1);
}
__global__ void scan_k() {
    __shared__ int wsum[32];
    __shared__ int carry;
    int tid = threadIdx.x, lane = tid & 31, wid = tid >> 5;
    if (tid == 0) carry = 0;
    __syncthreads();
    for (int base = 0; base < N; base += 1024) {
        int i = base + tid;
        int v = (i < N) ? g_deg[i] : 0;
        int x = v;
        #pragma unroll
        for (int o = 1; o < 32; o <<= 1) {
            int t = __shfl_up_sync(0xffffffffu, x, o);
            if (lane >= o) x += t;
        }
        if (lane == 31) wsum[wid] = x;
        __syncthreads();
        if (wid == 0) {
            int s = wsum[lane];
            #pragma unroll
            for (int o = 1; o < 32; o <<= 1) {
                int t = __shfl_up_sync(0xffffffffu, s, o);
                if (lane >= o) s += t;
            }
            wsum[lane] = s;
        }
        __syncthreads();
        int excl = x - v + (wid ? wsum[wid - 1] : 0) + carry;
        if (i < N) {
            g_row[i] = excl;
            g_fill[i] = excl;
            g_inv[i] = 1.0f / (float)(v > 0 ? v : 1);
        }
        __syncthreads();
        if (tid == 0) carry += wsum[31];
        __syncthreads();
    }
    if (tid == 0) g_row[N] = carry;
}
__global__ void scatter_k(const int* __restrict__ src, const int* __restrict__ dst) {
    int i = blockIdx.x * blockDim.x + threadIdx.x;
    if (i < E) {
        int pos = atomicAdd(&g_fill[dst[i]], 1);
        g_csr[pos] = src[i];
    }
}

// ---------------- prep: tf32-round weights (layout unchanged [k][n]) ----------
__global__ void wr_k(const float* __restrict__ W, int wsel, int n) {
    float* Wr = (wsel == 0) ? g_Wr0 : (wsel == 1 ? g_Wr1 : g_Wr2);
    int i = blockIdx.x * blockDim.x + threadIdx.x;
    if (i < n) Wr[i] = to_tf32(W[i]);
}

// ---------------- aggregation: mean of h[src] over in-edges -------------------
__global__ void __launch_bounds__(256)
agg_k(const float* __restrict__ h_in_p, int in_sel) {
    const float* h = (in_sel == 0) ? h_in_p : (in_sel == 1 ? g_h0 : g_h1);
    int tid = threadIdx.x, lane = tid & 31, w = tid >> 5;
    int node0 = blockIdx.x * 32 + w * 4;
    #pragma unroll
    for (int j = 0; j < 4; j++) {
        int node = node0 + j;
        if (node >= N) break;
        float4 acc = make_float4(0.f, 0.f, 0.f, 0.f);
        int beg = g_row[node], end = g_row[node + 1];
        int e = beg;
        for (; e + 4 <= end; e += 4) {
            int s0 = g_csr[e + 0], s1 = g_csr[e + 1];
            int s2 = g_csr[e + 2], s3 = g_csr[e + 3];
            float4 v0 = *(const float4*)(h + s0 * 128 + (lane << 2));
            float4 v1 = *(const float4*)(h + s1 * 128 + (lane << 2));
            float4 v2 = *(const float4*)(h + s2 * 128 + (lane << 2));
            float4 v3 = *(const float4*)(h + s3 * 128 + (lane << 2));
            acc.x += (v0.x + v1.x) + (v2.x + v3.x);
            acc.y += (v0.y + v1.y) + (v2.y + v3.y);
            acc.z += (v0.z + v1.z) + (v2.z + v3.z);
            acc.w += (v0.w + v1.w) + (v2.w + v3.w);
        }
        for (; e < end; ++e) {
            int s = g_csr[e];
            float4 v = *(const float4*)(h + s * 128 + (lane << 2));
            acc.x += v.x; acc.y += v.y; acc.z += v.z; acc.w += v.w;
        }
        float idg = g_inv[node];
        acc.x *= idg; acc.y *= idg; acc.z *= idg; acc.w *= idg;
        *(float4*)(g_mean + node * 128 + (lane << 2)) = acc;
    }
}

// ---------------- tf32 mma.sync GEMM layer ------------------------------------
// C[64 nodes, FOUT] per CTA. 8 warps in 2(m) x 4(n) grid; warp = 32 rows x FOUT/4.
// K=256 in two smem-staged halves: half 0 = self h, half 1 = mean.
// smem: W-half [128][FOUT+8], A [64][132] (pitches chosen for 0 bank conflicts).
template <int FOUT, bool RELU>
__global__ void __launch_bounds__(256)
gemm_k(const float* __restrict__ hself_p, int self_sel,
       const float* __restrict__ bias,
       float* __restrict__ out_p, int out_sel, int wsel) {
    const float* hs = (self_sel == 0) ? hself_p : (self_sel == 1 ? g_h0 : g_h1);
    float* of = (out_sel == 0) ? out_p : (out_sel == 1 ? g_h0 : g_h1);
    const float* Wr = (wsel == 0) ? g_Wr0 : (wsel == 1 ? g_Wr1 : g_Wr2);

    constexpr int WP = FOUT + 8;     // W smem pitch (floats)
    constexpr int AP = 132;          // A smem pitch
    constexpr int NT = FOUT / 32;    // n8-tiles per warp (4 or 2)
    extern __shared__ float smem[];
    float* sW = smem;                // [128][WP]
    float* sA = smem + 128 * WP;     // [64][AP]

    int tid = threadIdx.x, lane = tid & 31, w = tid >> 5;
    int g = lane >> 2, tg = lane & 3;
    int wm = w & 1, wn = w >> 1;
    int node_base = blockIdx.x * 64;

    float c[2][NT][4];
    #pragma unroll
    for (int mt = 0; mt < 2; mt++)
        #pragma unroll
        for (int nt = 0; nt < NT; nt++)
            #pragma unroll
            for (int i = 0; i < 4; i++) c[mt][nt][i] = 0.f;

    #pragma unroll
    for (int half = 0; half < 2; half++) {
        // ---- stage W half: rows k = half*128 .. +128 ----
        const float* srcW = Wr + half * 128 * FOUT;
        for (int idx = tid; idx < 128 * (FOUT / 4); idx += 256) {
            int k = idx / (FOUT / 4);
            int c4 = (idx % (FOUT / 4)) * 4;
            float4 v = *(const float4*)(srcW + k * FOUT + c4);
            *(float4*)(sW + k * WP + c4) = v;
        }
        // ---- stage A half (tf32-rounded) ----
        const float* srcA = (half == 0) ? hs : g_mean;
        for (int idx = tid; idx < 64 * 32; idx += 256) {
            int r = idx >> 5;
            int c4 = (idx & 31) << 2;
            int node = node_base + r;
            float4 v = make_float4(0.f, 0.f, 0.f, 0.f);
            if (node < N) v = *(const float4*)(srcA + node * 128 + c4);
            v.x = to_tf32(v.x); v.y = to_tf32(v.y);
            v.z = to_tf32(v.z); v.w = to_tf32(v.w);
            *(float4*)(sA + r * AP + c4) = v;
        }
        __syncthreads();

        // ---- 16 k-steps of m16n8k8 ----
        #pragma unroll 4
        for (int s = 0; s < 16; s++) {
            int k = s * 8;
            uint32_t a[2][4];
            #pragma unroll
            for (int mt = 0; mt < 2; mt++) {
                int r0 = wm * 32 + mt * 16 + g;
                a[mt][0] = __float_as_uint(sA[r0 * AP + k + tg]);
                a[mt][1] = __float_as_uint(sA[(r0 + 8) * AP + k + tg]);
                a[mt][2] = __float_as_uint(sA[r0 * AP + k + tg + 4]);
                a[mt][3] = __float_as_uint(sA[(r0 + 8) * AP + k + tg + 4]);
            }
            #pragma unroll
            for (int nt = 0; nt < NT; nt++) {
                int col = wn * (FOUT / 4) + nt * 8 + g;
                uint32_t b0 = __float_as_uint(sW[(k + tg) * WP + col]);
                uint32_t b1 = __float_as_uint(sW[(k + tg + 4) * WP + col]);
                #pragma unroll
                for (int mt = 0; mt < 2; mt++) {
                    asm volatile(
                        "mma.sync.aligned.m16n8k8.row.col.f32.tf32.tf32.f32 "
                        "{%0,%1,%2,%3}, {%4,%5,%6,%7}, {%8,%9}, {%0,%1,%2,%3};"
                        : "+f"(c[mt][nt][0]), "+f"(c[mt][nt][1]),
                          "+f"(c[mt][nt][2]), "+f"(c[mt][nt][3])
                        : "r"(a[mt][0]), "r"(a[mt][1]), "r"(a[mt][2]), "r"(a[mt][3]),
                          "r"(b0), "r"(b1));
                }
            }
        }
        __syncthreads();
    }

    // ---- epilogue: bias + relu + store ----
    #pragma unroll
    for (int nt = 0; nt < NT; nt++) {
        int col = wn * (FOUT / 4) + nt * 8 + tg * 2;
        float bx = __ldg(bias + col), by = __ldg(bias + col + 1);
        #pragma unroll
        for (int mt = 0; mt < 2; mt++) {
            #pragma unroll
            for (int hrow = 0; hrow < 2; hrow++) {
                int node = node_base + wm * 32 + mt * 16 + g + hrow * 8;
                if (node >= N) continue;
                float ox = c[mt][nt][hrow * 2 + 0] + bx;
                float oy = c[mt][nt][hrow * 2 + 1] + by;
                if (RELU) { ox = fmaxf(ox, 0.f); oy = fmaxf(oy, 0.f); }
                *(float2*)(of + node * FOUT + col) = make_float2(ox, oy);
            }
        }
    }
}

// ---------------- launcher ----------------------------------------------------
extern "C" void kernel_launch(void* const* d_in, const int* in_sizes, int n_in,
                              void* d_out, int out_size) {
    const float* feat = (const float*)d_in[0];
    const int*   src  = (const int*)d_in[1];
    const int*   dst  = (const int*)d_in[2];
    const float* W0   = (const float*)d_in[3];
    const float* b0   = (const float*)d_in[4];
    const float* W1   = (const float*)d_in[5];
    const float* b1   = (const float*)d_in[6];
    const float* W2   = (const float*)d_in[7];
    const float* b2   = (const float*)d_in[8];
    float* out = (float*)d_out;

    const int smem128 = (128 * (128 + 8) + 64 * 132) * 4;   // 103,424 B
    const int smem64  = (128 * ( 64 + 8) + 64 * 132) * 4;   //  70,656 B
    cudaFuncSetAttribute(gemm_k<128, true >, cudaFuncAttributeMaxDynamicSharedMemorySize, smem128);
    cudaFuncSetAttribute(gemm_k< 64, false>, cudaFuncAttributeMaxDynamicSharedMemorySize, smem64);

    const int TB = 256;
    zero_deg_k<<<(N + TB - 1) / TB, TB>>>();
    count_k<<<(E + TB - 1) / TB, TB>>>(dst);
    scan_k<<<1, 1024>>>();
    scatter_k<<<(E + TB - 1) / TB, TB>>>(src, dst);

    wr_k<<<(256 * 128 + TB - 1) / TB, TB>>>(W0, 0, 256 * 128);
    wr_k<<<(256 * 128 + TB - 1) / TB, TB>>>(W1, 1, 256 * 128);
    wr_k<<<(256 * 64  + TB - 1) / TB, TB>>>(W2, 2, 256 * 64);

    int ablocks = (N + 31) / 32;     // 1563
    int gblocks = (N + 63) / 64;     // 782

    agg_k<<<ablocks, TB>>>(feat, 0);
    gemm_k<128, true ><<<gblocks, TB, smem128>>>(feat, 0, b0, nullptr, 1, 0);
    agg_k<<<ablocks, TB>>>(nullptr, 1);
    gemm_k<128, true ><<<gblocks, TB, smem128>>>(nullptr, 1, b1, nullptr, 2, 1);
    agg_k<<<ablocks, TB>>>(nullptr, 2);
    gemm_k< 64, false><<<gblocks, TB, smem64>>>(nullptr, 2, b2, out, 0, 2);
}

// round 6
// speedup vs baseline: 2.2353x; 1.0605x over previous
#include <cuda_runtime.h>
#include <cuda_bf16.h>
#include <cstdint>

static constexpr int N = 50000;
static constexpr int E = 1600000;

// ---------------- scratch -----------------------------------------------------
__device__ __align__(16) float g_h0[N * 128];
__device__ __align__(16) float g_h1[N * 128];
__device__ __align__(16) float g_mean[N * 128];
__device__ __align__(16) __nv_bfloat16 g_bA[N * 128];   // bf16 shadows for gather
__device__ __align__(16) __nv_bfloat16 g_bB[N * 128];
__device__ __align__(16) float g_Wr0[256 * 128];        // tf32-rounded, [k][n]
__device__ __align__(16) float g_Wr1[256 * 128];
__device__ __align__(16) float g_Wr2[256 * 64];
__device__ int   g_deg[N];
__device__ int   g_row[N + 1];
__device__ int   g_fill[N];
__device__ int   g_csr[E];
__device__ float g_inv[N];

// cvt.rna.tf32.f32 needs a .b32 destination -> go through a uint register.
__device__ __forceinline__ float to_tf32(float x) {
    uint32_t u;
    asm("cvt.rna.tf32.f32 %0, %1;" : "=r"(u) : "f"(x));
    return __uint_as_float(u);
}

// ---------------- CSR build ---------------------------------------------------
__global__ void zero_deg_k() {
    int i = blockIdx.x * blockDim.x + threadIdx.x;
    if (i < N) g_deg[i] = 0;
}
__global__ void count_k(const int* __restrict__ dst) {
    int i = blockIdx.x * blockDim.x + threadIdx.x;
    if (i < E) atomicAdd(&g_deg[dst[i]], 1);
}
__global__ void scan_k() {
    __shared__ int wsum[32];
    __shared__ int carry;
    int tid = threadIdx.x, lane = tid & 31, wid = tid >> 5;
    if (tid == 0) carry = 0;
    __syncthreads();
    for (int base = 0; base < N; base += 1024) {
        int i = base + tid;
        int v = (i < N) ? g_deg[i] : 0;
        int x = v;
        #pragma unroll
        for (int o = 1; o < 32; o <<= 1) {
            int t = __shfl_up_sync(0xffffffffu, x, o);
            if (lane >= o) x += t;
        }
        if (lane == 31) wsum[wid] = x;
        __syncthreads();
        if (wid == 0) {
            int s = wsum[lane];
            #pragma unroll
            for (int o = 1; o < 32; o <<= 1) {
                int t = __shfl_up_sync(0xffffffffu, s, o);
                if (lane >= o) s += t;
            }
            wsum[lane] = s;
        }
        __syncthreads();
        int excl = x - v + (wid ? wsum[wid - 1] : 0) + carry;
        if (i < N) {
            g_row[i] = excl;
            g_fill[i] = excl;
            g_inv[i] = 1.0f / (float)(v > 0 ? v : 1);
        }
        __syncthreads();
        if (tid == 0) carry += wsum[31];
        __syncthreads();
    }
    if (tid == 0) g_row[N] = carry;
}
__global__ void scatter_k(const int* __restrict__ src, const int* __restrict__ dst) {
    int i = blockIdx.x * blockDim.x + threadIdx.x;
    if (i < E) {
        int pos = atomicAdd(&g_fill[dst[i]], 1);
        g_csr[pos] = src[i];
    }
}

// ---------------- prep: tf32 weights + bf16 feature shadow --------------------
__global__ void wr_k(const float* __restrict__ W, int wsel, int n) {
    float* Wr = (wsel == 0) ? g_Wr0 : (wsel == 1 ? g_Wr1 : g_Wr2);
    int i = blockIdx.x * blockDim.x + threadIdx.x;
    if (i < n) Wr[i] = to_tf32(W[i]);
}
__global__ void prep_feat_k(const float* __restrict__ f) {
    int i = blockIdx.x * blockDim.x + threadIdx.x;
    if (i < N * 64) {
        float2 v = ((const float2*)f)[i];
        ((__nv_bfloat162*)g_bA)[i] = __float22bfloat162_rn(v);
    }
}

// ---------------- aggregation: mean of bf16 h[src] over in-edges --------------
// warp owns 4 nodes, lane covers features k = lane*4..lane*4+3 (uint2 = 4 bf16)
__global__ void __launch_bounds__(256)
agg_k(int gat_sel) {
    const __nv_bfloat16* h = (gat_sel == 0) ? g_bA : g_bB;
    int tid = threadIdx.x, lane = tid & 31, w = tid >> 5;
    int node0 = blockIdx.x * 32 + w * 4;
    int k4 = lane * 4;
    #pragma unroll
    for (int j = 0; j < 4; j++) {
        int node = node0 + j;
        if (node >= N) break;
        float4 acc = make_float4(0.f, 0.f, 0.f, 0.f);
        int beg = g_row[node], end = g_row[node + 1];
        int e = beg;
        for (; e + 4 <= end; e += 4) {
            int s0 = g_csr[e + 0], s1 = g_csr[e + 1];
            int s2 = g_csr[e + 2], s3 = g_csr[e + 3];
            uint2 r0 = *(const uint2*)(h + s0 * 128 + k4);
            uint2 r1 = *(const uint2*)(h + s1 * 128 + k4);
            uint2 r2 = *(const uint2*)(h + s2 * 128 + k4);
            uint2 r3 = *(const uint2*)(h + s3 * 128 + k4);
            acc.x += (__uint_as_float(r0.x << 16) + __uint_as_float(r1.x << 16))
                   + (__uint_as_float(r2.x << 16) + __uint_as_float(r3.x << 16));
            acc.y += (__uint_as_float(r0.x & 0xffff0000u) + __uint_as_float(r1.x & 0xffff0000u))
                   + (__uint_as_float(r2.x & 0xffff0000u) + __uint_as_float(r3.x & 0xffff0000u));
            acc.z += (__uint_as_float(r0.y << 16) + __uint_as_float(r1.y << 16))
                   + (__uint_as_float(r2.y << 16) + __uint_as_float(r3.y << 16));
            acc.w += (__uint_as_float(r0.y & 0xffff0000u) + __uint_as_float(r1.y & 0xffff0000u))
                   + (__uint_as_float(r2.y & 0xffff0000u) + __uint_as_float(r3.y & 0xffff0000u));
        }
        for (; e < end; ++e) {
            int s = g_csr[e];
            uint2 r = *(const uint2*)(h + s * 128 + k4);
            acc.x += __uint_as_float(r.x << 16);
            acc.y += __uint_as_float(r.x & 0xffff0000u);
            acc.z += __uint_as_float(r.y << 16);
            acc.w += __uint_as_float(r.y & 0xffff0000u);
        }
        float idg = g_inv[node];
        acc.x *= idg; acc.y *= idg; acc.z *= idg; acc.w *= idg;
        *(float4*)(g_mean + node * 128 + k4) = acc;
    }
}

// ---------------- tf32 mma.sync GEMM layer ------------------------------------
// C[64 nodes, FOUT] per CTA. 8 warps in 2(m) x 4(n) grid.
// K=256 in two smem-staged halves: half 0 = self h (fp32), half 1 = mean (fp32).
// Epilogue also writes a bf16 shadow of the output when SHADOW != 0.
template <int FOUT, bool RELU, int SHADOW>   // SHADOW: 0 none, 1 g_bB, 2 g_bA
__global__ void __launch_bounds__(256)
gemm_k(const float* __restrict__ hself_p, int self_sel,
       const float* __restrict__ bias,
       float* __restrict__ out_p, int out_sel, int wsel) {
    const float* hs = (self_sel == 0) ? hself_p : (self_sel == 1 ? g_h0 : g_h1);
    float* of = (out_sel == 0) ? out_p : (out_sel == 1 ? g_h0 : g_h1);
    const float* Wr = (wsel == 0) ? g_Wr0 : (wsel == 1 ? g_Wr1 : g_Wr2);
    __nv_bfloat16* sh = (SHADOW == 1) ? g_bB : g_bA;

    constexpr int WP = FOUT + 8;
    constexpr int AP = 132;
    constexpr int NT = FOUT / 32;
    extern __shared__ float smem[];
    float* sW = smem;                // [128][WP]
    float* sA = smem + 128 * WP;     // [64][AP]

    int tid = threadIdx.x, lane = tid & 31, w = tid >> 5;
    int g = lane >> 2, tg = lane & 3;
    int wm = w & 1, wn = w >> 1;
    int node_base = blockIdx.x * 64;

    float c[2][NT][4];
    #pragma unroll
    for (int mt = 0; mt < 2; mt++)
        #pragma unroll
        for (int nt = 0; nt < NT; nt++)
            #pragma unroll
            for (int i = 0; i < 4; i++) c[mt][nt][i] = 0.f;

    #pragma unroll
    for (int half = 0; half < 2; half++) {
        const float* srcW = Wr + half * 128 * FOUT;
        for (int idx = tid; idx < 128 * (FOUT / 4); idx += 256) {
            int k = idx / (FOUT / 4);
            int c4 = (idx % (FOUT / 4)) * 4;
            float4 v = *(const float4*)(srcW + k * FOUT + c4);
            *(float4*)(sW + k * WP + c4) = v;
        }
        const float* srcA = (half == 0) ? hs : g_mean;
        for (int idx = tid; idx < 64 * 32; idx += 256) {
            int r = idx >> 5;
            int c4 = (idx & 31) << 2;
            int node = node_base + r;
            float4 v = make_float4(0.f, 0.f, 0.f, 0.f);
            if (node < N) v = *(const float4*)(srcA + node * 128 + c4);
            v.x = to_tf32(v.x); v.y = to_tf32(v.y);
            v.z = to_tf32(v.z); v.w = to_tf32(v.w);
            *(float4*)(sA + r * AP + c4) = v;
        }
        __syncthreads();

        #pragma unroll 4
        for (int s = 0; s < 16; s++) {
            int k = s * 8;
            uint32_t a[2][4];
            #pragma unroll
            for (int mt = 0; mt < 2; mt++) {
                int r0 = wm * 32 + mt * 16 + g;
                a[mt][0] = __float_as_uint(sA[r0 * AP + k + tg]);
                a[mt][1] = __float_as_uint(sA[(r0 + 8) * AP + k + tg]);
                a[mt][2] = __float_as_uint(sA[r0 * AP + k + tg + 4]);
                a[mt][3] = __float_as_uint(sA[(r0 + 8) * AP + k + tg + 4]);
            }
            #pragma unroll
            for (int nt = 0; nt < NT; nt++) {
                int col = wn * (FOUT / 4) + nt * 8 + g;
                uint32_t b0 = __float_as_uint(sW[(k + tg) * WP + col]);
                uint32_t b1 = __float_as_uint(sW[(k + tg + 4) * WP + col]);
                #pragma unroll
                for (int mt = 0; mt < 2; mt++) {
                    asm volatile(
                        "mma.sync.aligned.m16n8k8.row.col.f32.tf32.tf32.f32 "
                        "{%0,%1,%2,%3}, {%4,%5,%6,%7}, {%8,%9}, {%0,%1,%2,%3};"
                        : "+f"(c[mt][nt][0]), "+f"(c[mt][nt][1]),
                          "+f"(c[mt][nt][2]), "+f"(c[mt][nt][3])
                        : "r"(a[mt][0]), "r"(a[mt][1]), "r"(a[mt][2]), "r"(a[mt][3]),
                          "r"(b0), "r"(b1));
                }
            }
        }
        __syncthreads();
    }

    // ---- epilogue: bias + relu + fp32 store (+ bf16 shadow) ----
    #pragma unroll
    for (int nt = 0; nt < NT; nt++) {
        int col = wn * (FOUT / 4) + nt * 8 + tg * 2;
        float bx = __ldg(bias + col), by = __ldg(bias + col + 1);
        #pragma unroll
        for (int mt = 0; mt < 2; mt++) {
            #pragma unroll
            for (int hrow = 0; hrow < 2; hrow++) {
                int node = node_base + wm * 32 + mt * 16 + g + hrow * 8;
                if (node >= N) continue;
                float ox = c[mt][nt][hrow * 2 + 0] + bx;
                float oy = c[mt][nt][hrow * 2 + 1] + by;
                if (RELU) { ox = fmaxf(ox, 0.f); oy = fmaxf(oy, 0.f); }
                *(float2*)(of + node * FOUT + col) = make_float2(ox, oy);
                if (SHADOW != 0) {
                    __nv_bfloat162 p = __float22bfloat162_rn(make_float2(ox, oy));
                    *(__nv_bfloat162*)(sh + node * 128 + col) = p;
                }
            }
        }
    }
}

// ---------------- launcher ----------------------------------------------------
extern "C" void kernel_launch(void* const* d_in, const int* in_sizes, int n_in,
                              void* d_out, int out_size) {
    const float* feat = (const float*)d_in[0];
    const int*   src  = (const int*)d_in[1];
    const int*   dst  = (const int*)d_in[2];
    const float* W0   = (const float*)d_in[3];
    const float* b0   = (const float*)d_in[4];
    const float* W1   = (const float*)d_in[5];
    const float* b1   = (const float*)d_in[6];
    const float* W2   = (const float*)d_in[7];
    const float* b2   = (const float*)d_in[8];
    float* out = (float*)d_out;

    const int smem128 = (128 * (128 + 8) + 64 * 132) * 4;   // 103,424 B
    const int smem64  = (128 * ( 64 + 8) + 64 * 132) * 4;   //  70,656 B
    cudaFuncSetAttribute(gemm_k<128, true, 1>, cudaFuncAttributeMaxDynamicSharedMemorySize, smem128);
    cudaFuncSetAttribute(gemm_k<128, true, 2>, cudaFuncAttributeMaxDynamicSharedMemorySize, smem128);
    cudaFuncSetAttribute(gemm_k< 64, false, 0>, cudaFuncAttributeMaxDynamicSharedMemorySize, smem64);

    const int TB = 256;
    zero_deg_k<<<(N + TB - 1) / TB, TB>>>();
    count_k<<<(E + TB - 1) / TB, TB>>>(dst);
    scan_k<<<1, 1024>>>();
    scatter_k<<<(E + TB - 1) / TB, TB>>>(src, dst);

    wr_k<<<(256 * 128 + TB - 1) / TB, TB>>>(W0, 0, 256 * 128);
    wr_k<<<(256 * 128 + TB - 1) / TB, TB>>>(W1, 1, 256 * 128);
    wr_k<<<(256 * 64  + TB - 1) / TB, TB>>>(W2, 2, 256 * 64);
    prep_feat_k<<<(N * 64 + TB - 1) / TB, TB>>>(feat);

    int ablocks = (N + 31) / 32;     // 1563
    int gblocks = (N + 63) / 64;     // 782

    // layer 0: gather bf16 feat (g_bA) -> mean; self = fp32 feat; out g_h0 + shadow g_bB
    agg_k<<<ablocks, TB>>>(0);
    gemm_k<128, true, 1><<<gblocks, TB, smem128>>>(feat, 0, b0, nullptr, 1, 0);
    // layer 1: gather g_bB -> mean; self = g_h0; out g_h1 + shadow g_bA
    agg_k<<<ablocks, TB>>>(1);
    gemm_k<128, true, 2><<<gblocks, TB, smem128>>>(nullptr, 1, b1, nullptr, 2, 1);
    // layer 2: gather g_bA -> mean; self = g_h1; out = dout
    agg_k<<<ablocks, TB>>>(0);
    gemm_k< 64, false, 0><<<gblocks, TB, smem64>>>(nullptr, 2, b2, out, 0, 2);
}

// round 7
// speedup vs baseline: 2.3611x; 1.0563x over previous
#include <cuda_runtime.h>
#include <cuda_bf16.h>
#include <cstdint>

static constexpr int N = 50000;
static constexpr int E = 1600000;

// ---------------- scratch -----------------------------------------------------
__device__ __align__(16) float g_h0[N * 128];
__device__ __align__(16) float g_h1[N * 128];
__device__ __align__(16) float g_mean[N * 128];
__device__ __align__(16) __nv_bfloat16 g_bA[N * 128];   // bf16 shadows for gather
__device__ __align__(16) __nv_bfloat16 g_bB[N * 128];
__device__ __align__(16) float g_Wr0[256 * 128];        // tf32-rounded, [k][n]
__device__ __align__(16) float g_Wr1[256 * 128];
__device__ __align__(16) float g_Wr2[256 * 64];
__device__ int   g_deg[N];
__device__ int   g_row[N + 1];
__device__ int   g_fill[N];
__device__ int   g_csr[E];
__device__ float g_inv[N];

// cvt.rna.tf32.f32 needs a .b32 destination -> go through a uint register.
__device__ __forceinline__ float to_tf32(float x) {
    uint32_t u;
    asm("cvt.rna.tf32.f32 %0, %1;" : "=r"(u) : "f"(x));
    return __uint_as_float(u);
}
// L2-only load (skip L1 allocation; gather rows have ~0% L1 hit rate)
__device__ __forceinline__ uint2 ldcg_u2(const void* p) {
    uint2 r;
    asm volatile("ld.global.cg.v2.u32 {%0,%1}, [%2];" : "=r"(r.x), "=r"(r.y) : "l"(p));
    return r;
}

// ---------------- CSR build ---------------------------------------------------
__global__ void zero_deg_k() {
    int i = blockIdx.x * blockDim.x + threadIdx.x;
    if (i < N) g_deg[i] = 0;
}
__global__ void count_k(const int* __restrict__ dst) {
    int i = blockIdx.x * blockDim.x + threadIdx.x;
    if (i < E) atomicAdd(&g_deg[dst[i]], 1);
}
__global__ void scan_k() {
    __shared__ int wsum[32];
    __shared__ int carry;
    int tid = threadIdx.x, lane = tid & 31, wid = tid >> 5;
    if (tid == 0) carry = 0;
    __syncthreads();
    for (int base = 0; base < N; base += 1024) {
        int i = base + tid;
        int v = (i < N) ? g_deg[i] : 0;
        int x = v;
        #pragma unroll
        for (int o = 1; o < 32; o <<= 1) {
            int t = __shfl_up_sync(0xffffffffu, x, o);
            if (lane >= o) x += t;
        }
        if (lane == 31) wsum[wid] = x;
        __syncthreads();
        if (wid == 0) {
            int s = wsum[lane];
            #pragma unroll
            for (int o = 1; o < 32; o <<= 1) {
                int t = __shfl_up_sync(0xffffffffu, s, o);
                if (lane >= o) s += t;
            }
            wsum[lane] = s;
        }
        __syncthreads();
        int excl = x - v + (wid ? wsum[wid - 1] : 0) + carry;
        if (i < N) {
            g_row[i] = excl;
            g_fill[i] = excl;
            g_inv[i] = 1.0f / (float)(v > 0 ? v : 1);
        }
        __syncthreads();
        if (tid == 0) carry += wsum[31];
        __syncthreads();
    }
    if (tid == 0) g_row[N] = carry;
}
__global__ void scatter_k(const int* __restrict__ src, const int* __restrict__ dst) {
    int i = blockIdx.x * blockDim.x + threadIdx.x;
    if (i < E) {
        int pos = atomicAdd(&g_fill[dst[i]], 1);
        g_csr[pos] = src[i];
    }
}

// ---------------- prep: tf32 weights + bf16 feature shadow --------------------
__global__ void wr_k(const float* __restrict__ W, int wsel, int n) {
    float* Wr = (wsel == 0) ? g_Wr0 : (wsel == 1 ? g_Wr1 : g_Wr2);
    int i = blockIdx.x * blockDim.x + threadIdx.x;
    if (i < n) Wr[i] = to_tf32(W[i]);
}
__global__ void prep_feat_k(const float* __restrict__ f) {
    int i = blockIdx.x * blockDim.x + threadIdx.x;
    if (i < N * 64) {
        float2 v = ((const float2*)f)[i];
        ((__nv_bfloat162*)g_bA)[i] = __float22bfloat162_rn(v);
    }
}

// ---------------- aggregation: mean of bf16 h[src] over in-edges --------------
// Warp owns 2 nodes (more warps -> better latency hiding); lane covers features
// k = lane*4..lane*4+3. Edge loop unrolled 8-deep -> 8 outstanding L2 loads per
// dependency step. Gather loads bypass L1 (ld.global.cg).
__global__ void __launch_bounds__(256)
agg_k(int gat_sel) {
    const __nv_bfloat16* h = (gat_sel == 0) ? g_bA : g_bB;
    int tid = threadIdx.x, lane = tid & 31, w = tid >> 5;
    int node0 = blockIdx.x * 16 + w * 2;
    int k4 = lane * 4;
    #pragma unroll
    for (int j = 0; j < 2; j++) {
        int node = node0 + j;
        if (node >= N) break;
        float4 acc = make_float4(0.f, 0.f, 0.f, 0.f);
        int beg = g_row[node], end = g_row[node + 1];
        int e = beg;
        for (; e + 8 <= end; e += 8) {
            int s[8];
            #pragma unroll
            for (int q = 0; q < 8; q++) s[q] = g_csr[e + q];
            uint2 r[8];
            #pragma unroll
            for (int q = 0; q < 8; q++) r[q] = ldcg_u2(h + s[q] * 128 + k4);
            float x0 = 0.f, y0 = 0.f, z0 = 0.f, w0 = 0.f;
            #pragma unroll
            for (int q = 0; q < 8; q++) {
                x0 += __uint_as_float(r[q].x << 16);
                y0 += __uint_as_float(r[q].x & 0xffff0000u);
                z0 += __uint_as_float(r[q].y << 16);
                w0 += __uint_as_float(r[q].y & 0xffff0000u);
            }
            acc.x += x0; acc.y += y0; acc.z += z0; acc.w += w0;
        }
        for (; e < end; ++e) {
            int s = g_csr[e];
            uint2 r = ldcg_u2(h + s * 128 + k4);
            acc.x += __uint_as_float(r.x << 16);
            acc.y += __uint_as_float(r.x & 0xffff0000u);
            acc.z += __uint_as_float(r.y << 16);
            acc.w += __uint_as_float(r.y & 0xffff0000u);
        }
        float idg = g_inv[node];
        acc.x *= idg; acc.y *= idg; acc.z *= idg; acc.w *= idg;
        *(float4*)(g_mean + node * 128 + k4) = acc;
    }
}

// ---------------- tf32 mma.sync GEMM layer ------------------------------------
// C[64 nodes, FOUT] per CTA. 8 warps in 2(m) x 4(n) grid.
// K=256 in two smem-staged halves: half 0 = self h (fp32), half 1 = mean (fp32).
// Epilogue also writes a bf16 shadow of the output when SHADOW != 0.
template <int FOUT, bool RELU, int SHADOW>   // SHADOW: 0 none, 1 g_bB, 2 g_bA
__global__ void __launch_bounds__(256)
gemm_k(const float* __restrict__ hself_p, int self_sel,
       const float* __restrict__ bias,
       float* __restrict__ out_p, int out_sel, int wsel) {
    const float* hs = (self_sel == 0) ? hself_p : (self_sel == 1 ? g_h0 : g_h1);
    float* of = (out_sel == 0) ? out_p : (out_sel == 1 ? g_h0 : g_h1);
    const float* Wr = (wsel == 0) ? g_Wr0 : (wsel == 1 ? g_Wr1 : g_Wr2);
    __nv_bfloat16* sh = (SHADOW == 1) ? g_bB : g_bA;

    constexpr int WP = FOUT + 8;
    constexpr int AP = 132;
    constexpr int NT = FOUT / 32;
    extern __shared__ float smem[];
    float* sW = smem;                // [128][WP]
    float* sA = smem + 128 * WP;     // [64][AP]

    int tid = threadIdx.x, lane = tid & 31, w = tid >> 5;
    int g = lane >> 2, tg = lane & 3;
    int wm = w & 1, wn = w >> 1;
    int node_base = blockIdx.x * 64;

    float c[2][NT][4];
    #pragma unroll
    for (int mt = 0; mt < 2; mt++)
        #pragma unroll
        for (int nt = 0; nt < NT; nt++)
            #pragma unroll
            for (int i = 0; i < 4; i++) c[mt][nt][i] = 0.f;

    #pragma unroll
    for (int half = 0; half < 2; half++) {
        const float* srcW = Wr + half * 128 * FOUT;
        for (int idx = tid; idx < 128 * (FOUT / 4); idx += 256) {
            int k = idx / (FOUT / 4);
            int c4 = (idx % (FOUT / 4)) * 4;
            float4 v = *(const float4*)(srcW + k * FOUT + c4);
            *(float4*)(sW + k * WP + c4) = v;
        }
        const float* srcA = (half == 0) ? hs : g_mean;
        for (int idx = tid; idx < 64 * 32; idx += 256) {
            int r = idx >> 5;
            int c4 = (idx & 31) << 2;
            int node = node_base + r;
            float4 v = make_float4(0.f, 0.f, 0.f, 0.f);
            if (node < N) v = *(const float4*)(srcA + node * 128 + c4);
            v.x = to_tf32(v.x); v.y = to_tf32(v.y);
            v.z = to_tf32(v.z); v.w = to_tf32(v.w);
            *(float4*)(sA + r * AP + c4) = v;
        }
        __syncthreads();

        #pragma unroll 4
        for (int s = 0; s < 16; s++) {
            int k = s * 8;
            uint32_t a[2][4];
            #pragma unroll
            for (int mt = 0; mt < 2; mt++) {
                int r0 = wm * 32 + mt * 16 + g;
                a[mt][0] = __float_as_uint(sA[r0 * AP + k + tg]);
                a[mt][1] = __float_as_uint(sA[(r0 + 8) * AP + k + tg]);
                a[mt][2] = __float_as_uint(sA[r0 * AP + k + tg + 4]);
                a[mt][3] = __float_as_uint(sA[(r0 + 8) * AP + k + tg + 4]);
            }
            #pragma unroll
            for (int nt = 0; nt < NT; nt++) {
                int col = wn * (FOUT / 4) + nt * 8 + g;
                uint32_t b0 = __float_as_uint(sW[(k + tg) * WP + col]);
                uint32_t b1 = __float_as_uint(sW[(k + tg + 4) * WP + col]);
                #pragma unroll
                for (int mt = 0; mt < 2; mt++) {
                    asm volatile(
                        "mma.sync.aligned.m16n8k8.row.col.f32.tf32.tf32.f32 "
                        "{%0,%1,%2,%3}, {%4,%5,%6,%7}, {%8,%9}, {%0,%1,%2,%3};"
                        : "+f"(c[mt][nt][0]), "+f"(c[mt][nt][1]),
                          "+f"(c[mt][nt][2]), "+f"(c[mt][nt][3])
                        : "r"(a[mt][0]), "r"(a[mt][1]), "r"(a[mt][2]), "r"(a[mt][3]),
                          "r"(b0), "r"(b1));
                }
            }
        }
        __syncthreads();
    }

    // ---- epilogue: bias + relu + fp32 store (+ bf16 shadow) ----
    #pragma unroll
    for (int nt = 0; nt < NT; nt++) {
        int col = wn * (FOUT / 4) + nt * 8 + tg * 2;
        float bx = __ldg(bias + col), by = __ldg(bias + col + 1);
        #pragma unroll
        for (int mt = 0; mt < 2; mt++) {
            #pragma unroll
            for (int hrow = 0; hrow < 2; hrow++) {
                int node = node_base + wm * 32 + mt * 16 + g + hrow * 8;
                if (node >= N) continue;
                float ox = c[mt][nt][hrow * 2 + 0] + bx;
                float oy = c[mt][nt][hrow * 2 + 1] + by;
                if (RELU) { ox = fmaxf(ox, 0.f); oy = fmaxf(oy, 0.f); }
                *(float2*)(of + node * FOUT + col) = make_float2(ox, oy);
                if (SHADOW != 0) {
                    __nv_bfloat162 p = __float22bfloat162_rn(make_float2(ox, oy));
                    *(__nv_bfloat162*)(sh + node * 128 + col) = p;
                }
            }
        }
    }
}

// ---------------- launcher ----------------------------------------------------
extern "C" void kernel_launch(void* const* d_in, const int* in_sizes, int n_in,
                              void* d_out, int out_size) {
    const float* feat = (const float*)d_in[0];
    const int*   src  = (const int*)d_in[1];
    const int*   dst  = (const int*)d_in[2];
    const float* W0   = (const float*)d_in[3];
    const float* b0   = (const float*)d_in[4];
    const float* W1   = (const float*)d_in[5];
    const float* b1   = (const float*)d_in[6];
    const float* W2   = (const float*)d_in[7];
    const float* b2   = (const float*)d_in[8];
    float* out = (float*)d_out;

    const int smem128 = (128 * (128 + 8) + 64 * 132) * 4;   // 103,424 B
    const int smem64  = (128 * ( 64 + 8) + 64 * 132) * 4;   //  70,656 B
    cudaFuncSetAttribute(gemm_k<128, true, 1>, cudaFuncAttributeMaxDynamicSharedMemorySize, smem128);
    cudaFuncSetAttribute(gemm_k<128, true, 2>, cudaFuncAttributeMaxDynamicSharedMemorySize, smem128);
    cudaFuncSetAttribute(gemm_k< 64, false, 0>, cudaFuncAttributeMaxDynamicSharedMemorySize, smem64);

    const int TB = 256;
    zero_deg_k<<<(N + TB - 1) / TB, TB>>>();
    count_k<<<(E + TB - 1) / TB, TB>>>(dst);
    scan_k<<<1, 1024>>>();
    scatter_k<<<(E + TB - 1) / TB, TB>>>(src, dst);

    wr_k<<<(256 * 128 + TB - 1) / TB, TB>>>(W0, 0, 256 * 128);
    wr_k<<<(256 * 128 + TB - 1) / TB, TB>>>(W1, 1, 256 * 128);
    wr_k<<<(256 * 64  + TB - 1) / TB, TB>>>(W2, 2, 256 * 64);
    prep_feat_k<<<(N * 64 + TB - 1) / TB, TB>>>(feat);

    int ablocks = (N + 15) / 16;     // 3125 (2 nodes/warp)
    int gblocks = (N + 63) / 64;     // 782

    // layer 0: gather bf16 feat (g_bA) -> mean; self = fp32 feat; out g_h0 + shadow g_bB
    agg_k<<<ablocks, TB>>>(0);
    gemm_k<128, true, 1><<<gblocks, TB, smem128>>>(feat, 0, b0, nullptr, 1, 0);
    // layer 1: gather g_bB -> mean; self = g_h0; out g_h1 + shadow g_bA
    agg_k<<<ablocks, TB>>>(1);
    gemm_k<128, true, 2><<<gblocks, TB, smem128>>>(nullptr, 1, b1, nullptr, 2, 1);
    // layer 2: gather g_bA -> mean; self = g_h1; out = dout
    agg_k<<<ablocks, TB>>>(0);
    gemm_k< 64, false, 0><<<gblocks, TB, smem64>>>(nullptr, 2, b2, out, 0, 2);
}

// round 8
// speedup vs baseline: 2.7230x; 1.1533x over previous
#include <cuda_runtime.h>
#include <cuda_bf16.h>
#include <cstdint>

static constexpr int N = 50000;
static constexpr int E = 1600000;
static constexpr int SCAN_B = 1024;
static constexpr int NBLK = (N + SCAN_B - 1) / SCAN_B;   // 49

// ---------------- scratch -----------------------------------------------------
__device__ __align__(16) float g_h0[N * 128];
__device__ __align__(16) float g_h1[N * 128];
__device__ __align__(16) float g_mean[N * 128];
__device__ __align__(16) __nv_bfloat16 g_bA[N * 128];   // bf16 shadows for gather
__device__ __align__(16) __nv_bfloat16 g_bB[N * 128];
__device__ __align__(16) float g_Wr0[256 * 128];        // tf32-rounded, [k][n]
__device__ __align__(16) float g_Wr1[256 * 128];
__device__ __align__(16) float g_Wr2[256 * 64];
__device__ int   g_deg[N];
__device__ int   g_row[N + 1];
__device__ int   g_fill[N];
__device__ int   g_csr[E];
__device__ float g_inv[N];
__device__ int   g_bsum[NBLK];

// cvt.rna.tf32.f32 needs a .b32 destination -> go through a uint register.
__device__ __forceinline__ float to_tf32(float x) {
    uint32_t u;
    asm("cvt.rna.tf32.f32 %0, %1;" : "=r"(u) : "f"(x));
    return __uint_as_float(u);
}
// L2-only load (skip L1 allocation; gather rows have ~0% L1 hit rate)
__device__ __forceinline__ uint2 ldcg_u2(const void* p) {
    uint2 r;
    asm volatile("ld.global.cg.v2.u32 {%0,%1}, [%2];" : "=r"(r.x), "=r"(r.y) : "l"(p));
    return r;
}

// ---------------- merged prep: zero deg + tf32 weights + bf16 features --------
__global__ void prep_all_k(const float* __restrict__ f,
                           const float* __restrict__ W0,
                           const float* __restrict__ W1,
                           const float* __restrict__ W2) {
    int i = blockIdx.x * blockDim.x + threadIdx.x;
    if (i < N * 64) {
        float2 v = ((const float2*)f)[i];
        ((__nv_bfloat162*)g_bA)[i] = __float22bfloat162_rn(v);
    }
    if (i < N) g_deg[i] = 0;
    if (i < 256 * 128) {
        g_Wr0[i] = to_tf32(W0[i]);
        g_Wr1[i] = to_tf32(W1[i]);
    }
    if (i < 256 * 64) g_Wr2[i] = to_tf32(W2[i]);
}

// ---------------- CSR build ---------------------------------------------------
__global__ void count_k(const int* __restrict__ dst) {
    int i = blockIdx.x * blockDim.x + threadIdx.x;
    if (i < E) atomicAdd(&g_deg[dst[i]], 1);
}

// block-local exclusive scan of g_deg -> g_row (no global offset); block sums
__global__ void __launch_bounds__(SCAN_B) scanA_k() {
    __shared__ int wsum[32];
    int tid = threadIdx.x, lane = tid & 31, wid = tid >> 5;
    int i = blockIdx.x * SCAN_B + tid;
    int v = (i < N) ? g_deg[i] : 0;
    int x = v;
    #pragma unroll
    for (int o = 1; o < 32; o <<= 1) {
        int t = __shfl_up_sync(0xffffffffu, x, o);
        if (lane >= o) x += t;
    }
    if (lane == 31) wsum[wid] = x;
    __syncthreads();
    if (wid == 0) {
        int s = wsum[lane];
        #pragma unroll
        for (int o = 1; o < 32; o <<= 1) {
            int t = __shfl_up_sync(0xffffffffu, s, o);
            if (lane >= o) s += t;
        }
        wsum[lane] = s;
    }
    __syncthreads();
    int excl = x - v + (wid ? wsum[wid - 1] : 0);
    if (i < N) g_row[i] = excl;
    if (tid == SCAN_B - 1) g_bsum[blockIdx.x] = wsum[31];
}

// single small block: exclusive scan of the 49 block sums; writes g_row[N]
__global__ void scanB_k() {
    __shared__ int s[NBLK];
    int tid = threadIdx.x;
    if (tid < NBLK) s[tid] = g_bsum[tid];
    __syncthreads();
    if (tid == 0) {
        int run = 0;
        for (int b = 0; b < NBLK; b++) {
            int v = s[b];
            s[b] = run;
            run += v;
        }
        g_row[N] = run;
    }
    __syncthreads();
    if (tid < NBLK) g_bsum[tid] = s[tid];
}

// add block offsets; produce fill + inv_deg
__global__ void __launch_bounds__(SCAN_B) scanC_k() {
    int i = blockIdx.x * SCAN_B + threadIdx.x;
    if (i < N) {
        int r = g_row[i] + g_bsum[blockIdx.x];
        g_row[i] = r;
        g_fill[i] = r;
        int d = g_deg[i];
        g_inv[i] = 1.0f / (float)(d > 0 ? d : 1);
    }
}

__global__ void scatter_k(const int* __restrict__ src, const int* __restrict__ dst) {
    int i = blockIdx.x * blockDim.x + threadIdx.x;
    if (i < E) {
        int pos = atomicAdd(&g_fill[dst[i]], 1);
        g_csr[pos] = src[i];
    }
}

// ---------------- aggregation: mean of bf16 h[src] over in-edges --------------
// One node per warp (max resident-warp coverage); lane covers 4 features.
// 16-deep unroll -> 16 outstanding L2 loads per dependency step.
__global__ void __launch_bounds__(256)
agg_k(int gat_sel) {
    const __nv_bfloat16* h = (gat_sel == 0) ? g_bA : g_bB;
    int tid = threadIdx.x, lane = tid & 31, w = tid >> 5;
    int node = blockIdx.x * 8 + w;
    if (node >= N) return;
    int k4 = lane * 4;
    float4 acc = make_float4(0.f, 0.f, 0.f, 0.f);
    int beg = g_row[node], end = g_row[node + 1];
    int e = beg;
    for (; e + 16 <= end; e += 16) {
        int s[16];
        #pragma unroll
        for (int q = 0; q < 16; q++) s[q] = g_csr[e + q];
        uint2 r[16];
        #pragma unroll
        for (int q = 0; q < 16; q++) r[q] = ldcg_u2(h + s[q] * 128 + k4);
        float x0 = 0.f, y0 = 0.f, z0 = 0.f, w0 = 0.f;
        #pragma unroll
        for (int q = 0; q < 16; q++) {
            x0 += __uint_as_float(r[q].x << 16);
            y0 += __uint_as_float(r[q].x & 0xffff0000u);
            z0 += __uint_as_float(r[q].y << 16);
            w0 += __uint_as_float(r[q].y & 0xffff0000u);
        }
        acc.x += x0; acc.y += y0; acc.z += z0; acc.w += w0;
    }
    for (; e + 4 <= end; e += 4) {
        int s[4];
        #pragma unroll
        for (int q = 0; q < 4; q++) s[q] = g_csr[e + q];
        uint2 r[4];
        #pragma unroll
        for (int q = 0; q < 4; q++) r[q] = ldcg_u2(h + s[q] * 128 + k4);
        #pragma unroll
        for (int q = 0; q < 4; q++) {
            acc.x += __uint_as_float(r[q].x << 16);
            acc.y += __uint_as_float(r[q].x & 0xffff0000u);
            acc.z += __uint_as_float(r[q].y << 16);
            acc.w += __uint_as_float(r[q].y & 0xffff0000u);
        }
    }
    for (; e < end; ++e) {
        int s = g_csr[e];
        uint2 r = ldcg_u2(h + s * 128 + k4);
        acc.x += __uint_as_float(r.x << 16);
        acc.y += __uint_as_float(r.x & 0xffff0000u);
        acc.z += __uint_as_float(r.y << 16);
        acc.w += __uint_as_float(r.y & 0xffff0000u);
    }
    float idg = g_inv[node];
    acc.x *= idg; acc.y *= idg; acc.z *= idg; acc.w *= idg;
    *(float4*)(g_mean + node * 128 + k4) = acc;
}

// ---------------- tf32 mma.sync GEMM layer ------------------------------------
template <int FOUT, bool RELU, int SHADOW>   // SHADOW: 0 none, 1 g_bB, 2 g_bA
__global__ void __launch_bounds__(256)
gemm_k(const float* __restrict__ hself_p, int self_sel,
       const float* __restrict__ bias,
       float* __restrict__ out_p, int out_sel, int wsel) {
    const float* hs = (self_sel == 0) ? hself_p : (self_sel == 1 ? g_h0 : g_h1);
    float* of = (out_sel == 0) ? out_p : (out_sel == 1 ? g_h0 : g_h1);
    const float* Wr = (wsel == 0) ? g_Wr0 : (wsel == 1 ? g_Wr1 : g_Wr2);
    __nv_bfloat16* sh = (SHADOW == 1) ? g_bB : g_bA;

    constexpr int WP = FOUT + 8;
    constexpr int AP = 132;
    constexpr int NT = FOUT / 32;
    extern __shared__ float smem[];
    float* sW = smem;                // [128][WP]
    float* sA = smem + 128 * WP;     // [64][AP]

    int tid = threadIdx.x, lane = tid & 31, w = tid >> 5;
    int g = lane >> 2, tg = lane & 3;
    int wm = w & 1, wn = w >> 1;
    int node_base = blockIdx.x * 64;

    float c[2][NT][4];
    #pragma unroll
    for (int mt = 0; mt < 2; mt++)
        #pragma unroll
        for (int nt = 0; nt < NT; nt++)
            #pragma unroll
            for (int i = 0; i < 4; i++) c[mt][nt][i] = 0.f;

    #pragma unroll
    for (int half = 0; half < 2; half++) {
        const float* srcW = Wr + half * 128 * FOUT;
        for (int idx = tid; idx < 128 * (FOUT / 4); idx += 256) {
            int k = idx / (FOUT / 4);
            int c4 = (idx % (FOUT / 4)) * 4;
            float4 v = *(const float4*)(srcW + k * FOUT + c4);
            *(float4*)(sW + k * WP + c4) = v;
        }
        const float* srcA = (half == 0) ? hs : g_mean;
        for (int idx = tid; idx < 64 * 32; idx += 256) {
            int r = idx >> 5;
            int c4 = (idx & 31) << 2;
            int node = node_base + r;
            float4 v = make_float4(0.f, 0.f, 0.f, 0.f);
            if (node < N) v = *(const float4*)(srcA + node * 128 + c4);
            v.x = to_tf32(v.x); v.y = to_tf32(v.y);
            v.z = to_tf32(v.z); v.w = to_tf32(v.w);
            *(float4*)(sA + r * AP + c4) = v;
        }
        __syncthreads();

        #pragma unroll 4
        for (int s = 0; s < 16; s++) {
            int k = s * 8;
            uint32_t a[2][4];
            #pragma unroll
            for (int mt = 0; mt < 2; mt++) {
                int r0 = wm * 32 + mt * 16 + g;
                a[mt][0] = __float_as_uint(sA[r0 * AP + k + tg]);
                a[mt][1] = __float_as_uint(sA[(r0 + 8) * AP + k + tg]);
                a[mt][2] = __float_as_uint(sA[r0 * AP + k + tg + 4]);
                a[mt][3] = __float_as_uint(sA[(r0 + 8) * AP + k + tg + 4]);
            }
            #pragma unroll
            for (int nt = 0; nt < NT; nt++) {
                int col = wn * (FOUT / 4) + nt * 8 + g;
                uint32_t b0 = __float_as_uint(sW[(k + tg) * WP + col]);
                uint32_t b1 = __float_as_uint(sW[(k + tg + 4) * WP + col]);
                #pragma unroll
                for (int mt = 0; mt < 2; mt++) {
                    asm volatile(
                        "mma.sync.aligned.m16n8k8.row.col.f32.tf32.tf32.f32 "
                        "{%0,%1,%2,%3}, {%4,%5,%6,%7}, {%8,%9}, {%0,%1,%2,%3};"
                        : "+f"(c[mt][nt][0]), "+f"(c[mt][nt][1]),
                          "+f"(c[mt][nt][2]), "+f"(c[mt][nt][3])
                        : "r"(a[mt][0]), "r"(a[mt][1]), "r"(a[mt][2]), "r"(a[mt][3]),
                          "r"(b0), "r"(b1));
                }
            }
        }
        __syncthreads();
    }

    // ---- epilogue: bias + relu + fp32 store (+ bf16 shadow) ----
    #pragma unroll
    for (int nt = 0; nt < NT; nt++) {
        int col = wn * (FOUT / 4) + nt * 8 + tg * 2;
        float bx = __ldg(bias + col), by = __ldg(bias + col + 1);
        #pragma unroll
        for (int mt = 0; mt < 2; mt++) {
            #pragma unroll
            for (int hrow = 0; hrow < 2; hrow++) {
                int node = node_base + wm * 32 + mt * 16 + g + hrow * 8;
                if (node >= N) continue;
                float ox = c[mt][nt][hrow * 2 + 0] + bx;
                float oy = c[mt][nt][hrow * 2 + 1] + by;
                if (RELU) { ox = fmaxf(ox, 0.f); oy = fmaxf(oy, 0.f); }
                *(float2*)(of + node * FOUT + col) = make_float2(ox, oy);
                if (SHADOW != 0) {
                    __nv_bfloat162 p = __float22bfloat162_rn(make_float2(ox, oy));
                    *(__nv_bfloat162*)(sh + node * 128 + col) = p;
                }
            }
        }
    }
}

// ---------------- launcher ----------------------------------------------------
extern "C" void kernel_launch(void* const* d_in, const int* in_sizes, int n_in,
                              void* d_out, int out_size) {
    const float* feat = (const float*)d_in[0];
    const int*   src  = (const int*)d_in[1];
    const int*   dst  = (const int*)d_in[2];
    const float* W0   = (const float*)d_in[3];
    const float* b0   = (const float*)d_in[4];
    const float* W1   = (const float*)d_in[5];
    const float* b1   = (const float*)d_in[6];
    const float* W2   = (const float*)d_in[7];
    const float* b2   = (const float*)d_in[8];
    float* out = (float*)d_out;

    const int smem128 = (128 * (128 + 8) + 64 * 132) * 4;   // 103,424 B
    const int smem64  = (128 * ( 64 + 8) + 64 * 132) * 4;   //  70,656 B
    cudaFuncSetAttribute(gemm_k<128, true, 1>, cudaFuncAttributeMaxDynamicSharedMemorySize, smem128);
    cudaFuncSetAttribute(gemm_k<128, true, 2>, cudaFuncAttributeMaxDynamicSharedMemorySize, smem128);
    cudaFuncSetAttribute(gemm_k< 64, false, 0>, cudaFuncAttributeMaxDynamicSharedMemorySize, smem64);

    const int TB = 256;
    prep_all_k<<<(N * 64 + TB - 1) / TB, TB>>>(feat, W0, W1, W2);
    count_k<<<(E + TB - 1) / TB, TB>>>(dst);
    scanA_k<<<NBLK, SCAN_B>>>();
    scanB_k<<<1, 64>>>();
    scanC_k<<<NBLK, SCAN_B>>>();
    scatter_k<<<(E + TB - 1) / TB, TB>>>(src, dst);

    int ablocks = (N + 7) / 8;       // 6250 (1 node/warp)
    int gblocks = (N + 63) / 64;     // 782

    // layer 0: gather bf16 feat (g_bA) -> mean; self = fp32 feat; out g_h0 + shadow g_bB
    agg_k<<<ablocks, TB>>>(0);
    gemm_k<128, true, 1><<<gblocks, TB, smem128>>>(feat, 0, b0, nullptr, 1, 0);
    // layer 1: gather g_bB -> mean; self = g_h0; out g_h1 + shadow g_bA
    agg_k<<<ablocks, TB>>>(1);
    gemm_k<128, true, 2><<<gblocks, TB, smem128>>>(nullptr, 1, b1, nullptr, 2, 1);
    // layer 2: gather g_bA -> mean; self = g_h1; out = dout
    agg_k<<<ablocks, TB>>>(0);
    gemm_k< 64, false, 0><<<gblocks, TB, smem64>>>(nullptr, 2, b2, out, 0, 2);
}

// round 9
// speedup vs baseline: 2.7233x; 1.0001x over previous
#include <cuda_runtime.h>
#include <cuda_bf16.h>
#include <cstdint>

static constexpr int N = 50000;
static constexpr int E = 1600000;
static constexpr int SCAN_B = 1024;
static constexpr int NBLK = (N + SCAN_B - 1) / SCAN_B;   // 49

// ---------------- scratch -----------------------------------------------------
__device__ __align__(16) float g_h0[N * 128];
__device__ __align__(16) float g_h1[N * 128];
__device__ __align__(16) float g_mean[N * 128];
__device__ __align__(16) __nv_bfloat16 g_bA[N * 128];   // bf16 shadows for gather
__device__ __align__(16) __nv_bfloat16 g_bB[N * 128];
__device__ __align__(16) float g_Wr0[256 * 128];        // tf32-rounded, [k][n]
__device__ __align__(16) float g_Wr1[256 * 128];
__device__ __align__(16) float g_Wr2[256 * 64];
__device__ int   g_deg[N];
__device__ int   g_row[N + 1];
__device__ int   g_fill[N];
__device__ int   g_csr[E];
__device__ float g_inv[N];
__device__ int   g_bsum[NBLK];

// cvt.rna.tf32.f32 needs a .b32 destination -> go through a uint register.
__device__ __forceinline__ float to_tf32(float x) {
    uint32_t u;
    asm("cvt.rna.tf32.f32 %0, %1;" : "=r"(u) : "f"(x));
    return __uint_as_float(u);
}
// L2-only load (skip L1 allocation; gather rows have ~0% L1 hit rate)
__device__ __forceinline__ uint2 ldcg_u2(const void* p) {
    uint2 r;
    asm volatile("ld.global.cg.v2.u32 {%0,%1}, [%2];" : "=r"(r.x), "=r"(r.y) : "l"(p));
    return r;
}

// ---------------- merged prep: zero deg + tf32 weights + bf16 features --------
__global__ void prep_all_k(const float* __restrict__ f,
                           const float* __restrict__ W0,
                           const float* __restrict__ W1,
                           const float* __restrict__ W2) {
    int i = blockIdx.x * blockDim.x + threadIdx.x;
    if (i < N * 64) {
        float2 v = ((const float2*)f)[i];
        ((__nv_bfloat162*)g_bA)[i] = __float22bfloat162_rn(v);
    }
    if (i < N) g_deg[i] = 0;
    if (i < 256 * 128) {
        g_Wr0[i] = to_tf32(W0[i]);
        g_Wr1[i] = to_tf32(W1[i]);
    }
    if (i < 256 * 64) g_Wr2[i] = to_tf32(W2[i]);
}

// ---------------- CSR build ---------------------------------------------------
__global__ void count_k(const int* __restrict__ dst) {
    int i = blockIdx.x * blockDim.x + threadIdx.x;
    if (i < E) atomicAdd(&g_deg[dst[i]], 1);
}

// block-local exclusive scan of g_deg -> g_row (no global offset); block sums
__global__ void __launch_bounds__(SCAN_B) scanA_k() {
    __shared__ int wsum[32];
    int tid = threadIdx.x, lane = tid & 31, wid = tid >> 5;
    int i = blockIdx.x * SCAN_B + tid;
    int v = (i < N) ? g_deg[i] : 0;
    int x = v;
    #pragma unroll
    for (int o = 1; o < 32; o <<= 1) {
        int t = __shfl_up_sync(0xffffffffu, x, o);
        if (lane >= o) x += t;
    }
    if (lane == 31) wsum[wid] = x;
    __syncthreads();
    if (wid == 0) {
        int s = wsum[lane];
        #pragma unroll
        for (int o = 1; o < 32; o <<= 1) {
            int t = __shfl_up_sync(0xffffffffu, s, o);
            if (lane >= o) s += t;
        }
        wsum[lane] = s;
    }
    __syncthreads();
    int excl = x - v + (wid ? wsum[wid - 1] : 0);
    if (i < N) g_row[i] = excl;
    if (tid == SCAN_B - 1) g_bsum[blockIdx.x] = wsum[31];
}

// single small block: exclusive scan of the 49 block sums; writes g_row[N]
__global__ void scanB_k() {
    __shared__ int s[NBLK];
    int tid = threadIdx.x;
    if (tid < NBLK) s[tid] = g_bsum[tid];
    __syncthreads();
    if (tid == 0) {
        int run = 0;
        for (int b = 0; b < NBLK; b++) {
            int v = s[b];
            s[b] = run;
            run += v;
        }
        g_row[N] = run;
    }
    __syncthreads();
    if (tid < NBLK) g_bsum[tid] = s[tid];
}

// add block offsets; produce fill + inv_deg
__global__ void __launch_bounds__(SCAN_B) scanC_k() {
    int i = blockIdx.x * SCAN_B + threadIdx.x;
    if (i < N) {
        int r = g_row[i] + g_bsum[blockIdx.x];
        g_row[i] = r;
        g_fill[i] = r;
        int d = g_deg[i];
        g_inv[i] = 1.0f / (float)(d > 0 ? d : 1);
    }
}

__global__ void scatter_k(const int* __restrict__ src, const int* __restrict__ dst) {
    int i = blockIdx.x * blockDim.x + threadIdx.x;
    if (i < E) {
        int pos = atomicAdd(&g_fill[dst[i]], 1);
        g_csr[pos] = src[i];
    }
}

// ---------------- aggregation: mean of bf16 h[src] over in-edges --------------
// One node per warp (max resident-warp coverage); lane covers 4 features.
// 16-deep unroll -> 16 outstanding L2 loads per dependency step.
__global__ void __launch_bounds__(256)
agg_k(int gat_sel) {
    const __nv_bfloat16* h = (gat_sel == 0) ? g_bA : g_bB;
    int tid = threadIdx.x, lane = tid & 31, w = tid >> 5;
    int node = blockIdx.x * 8 + w;
    if (node >= N) return;
    int k4 = lane * 4;
    float4 acc = make_float4(0.f, 0.f, 0.f, 0.f);
    int beg = g_row[node], end = g_row[node + 1];
    int e = beg;
    for (; e + 16 <= end; e += 16) {
        int s[16];
        #pragma unroll
        for (int q = 0; q < 16; q++) s[q] = g_csr[e + q];
        uint2 r[16];
        #pragma unroll
        for (int q = 0; q < 16; q++) r[q] = ldcg_u2(h + s[q] * 128 + k4);
        float x0 = 0.f, y0 = 0.f, z0 = 0.f, w0 = 0.f;
        #pragma unroll
        for (int q = 0; q < 16; q++) {
            x0 += __uint_as_float(r[q].x << 16);
            y0 += __uint_as_float(r[q].x & 0xffff0000u);
            z0 += __uint_as_float(r[q].y << 16);
            w0 += __uint_as_float(r[q].y & 0xffff0000u);
        }
        acc.x += x0; acc.y += y0; acc.z += z0; acc.w += w0;
    }
    for (; e + 4 <= end; e += 4) {
        int s[4];
        #pragma unroll
        for (int q = 0; q < 4; q++) s[q] = g_csr[e + q];
        uint2 r[4];
        #pragma unroll
        for (int q = 0; q < 4; q++) r[q] = ldcg_u2(h + s[q] * 128 + k4);
        #pragma unroll
        for (int q = 0; q < 4; q++) {
            acc.x += __uint_as_float(r[q].x << 16);
            acc.y += __uint_as_float(r[q].x & 0xffff0000u);
            acc.z += __uint_as_float(r[q].y << 16);
            acc.w += __uint_as_float(r[q].y & 0xffff0000u);
        }
    }
    for (; e < end; ++e) {
        int s = g_csr[e];
        uint2 r = ldcg_u2(h + s * 128 + k4);
        acc.x += __uint_as_float(r.x << 16);
        acc.y += __uint_as_float(r.x & 0xffff0000u);
        acc.z += __uint_as_float(r.y << 16);
        acc.w += __uint_as_float(r.y & 0xffff0000u);
    }
    float idg = g_inv[node];
    acc.x *= idg; acc.y *= idg; acc.z *= idg; acc.w *= idg;
    *(float4*)(g_mean + node * 128 + k4) = acc;
}

// ---------------- tf32 mma.sync GEMM layer ------------------------------------
template <int FOUT, bool RELU, int SHADOW>   // SHADOW: 0 none, 1 g_bB, 2 g_bA
__global__ void __launch_bounds__(256)
gemm_k(const float* __restrict__ hself_p, int self_sel,
       const float* __restrict__ bias,
       float* __restrict__ out_p, int out_sel, int wsel) {
    const float* hs = (self_sel == 0) ? hself_p : (self_sel == 1 ? g_h0 : g_h1);
    float* of = (out_sel == 0) ? out_p : (out_sel == 1 ? g_h0 : g_h1);
    const float* Wr = (wsel == 0) ? g_Wr0 : (wsel == 1 ? g_Wr1 : g_Wr2);
    __nv_bfloat16* sh = (SHADOW == 1) ? g_bB : g_bA;

    constexpr int WP = FOUT + 8;
    constexpr int AP = 132;
    constexpr int NT = FOUT / 32;
    extern __shared__ float smem[];
    float* sW = smem;                // [128][WP]
    float* sA = smem + 128 * WP;     // [64][AP]

    int tid = threadIdx.x, lane = tid & 31, w = tid >> 5;
    int g = lane >> 2, tg = lane & 3;
    int wm = w & 1, wn = w >> 1;
    int node_base = blockIdx.x * 64;

    float c[2][NT][4];
    #pragma unroll
    for (int mt = 0; mt < 2; mt++)
        #pragma unroll
        for (int nt = 0; nt < NT; nt++)
            #pragma unroll
            for (int i = 0; i < 4; i++) c[mt][nt][i] = 0.f;

    #pragma unroll
    for (int half = 0; half < 2; half++) {
        const float* srcW = Wr + half * 128 * FOUT;
        for (int idx = tid; idx < 128 * (FOUT / 4); idx += 256) {
            int k = idx / (FOUT / 4);
            int c4 = (idx % (FOUT / 4)) * 4;
            float4 v = *(const float4*)(srcW + k * FOUT + c4);
            *(float4*)(sW + k * WP + c4) = v;
        }
        const float* srcA = (half == 0) ? hs : g_mean;
        for (int idx = tid; idx < 64 * 32; idx += 256) {
            int r = idx >> 5;
            int c4 = (idx & 31) << 2;
            int node = node_base + r;
            float4 v = make_float4(0.f, 0.f, 0.f, 0.f);
            if (node < N) v = *(const float4*)(srcA + node * 128 + c4);
            v.x = to_tf32(v.x); v.y = to_tf32(v.y);
            v.z = to_tf32(v.z); v.w = to_tf32(v.w);
            *(float4*)(sA + r * AP + c4) = v;
        }
        __syncthreads();

        #pragma unroll 4
        for (int s = 0; s < 16; s++) {
            int k = s * 8;
            uint32_t a[2][4];
            #pragma unroll
            for (int mt = 0; mt < 2; mt++) {
                int r0 = wm * 32 + mt * 16 + g;
                a[mt][0] = __float_as_uint(sA[r0 * AP + k + tg]);
                a[mt][1] = __float_as_uint(sA[(r0 + 8) * AP + k + tg]);
                a[mt][2] = __float_as_uint(sA[r0 * AP + k + tg + 4]);
                a[mt][3] = __float_as_uint(sA[(r0 + 8) * AP + k + tg + 4]);
            }
            #pragma unroll
            for (int nt = 0; nt < NT; nt++) {
                int col = wn * (FOUT / 4) + nt * 8 + g;
                uint32_t b0 = __float_as_uint(sW[(k + tg) * WP + col]);
                uint32_t b1 = __float_as_uint(sW[(k + tg + 4) * WP + col]);
                #pragma unroll
                for (int mt = 0; mt < 2; mt++) {
                    asm volatile(
                        "mma.sync.aligned.m16n8k8.row.col.f32.tf32.tf32.f32 "
                        "{%0,%1,%2,%3}, {%4,%5,%6,%7}, {%8,%9}, {%0,%1,%2,%3};"
                        : "+f"(c[mt][nt][0]), "+f"(c[mt][nt][1]),
                          "+f"(c[mt][nt][2]), "+f"(c[mt][nt][3])
                        : "r"(a[mt][0]), "r"(a[mt][1]), "r"(a[mt][2]), "r"(a[mt][3]),
                          "r"(b0), "r"(b1));
                }
            }
        }
        __syncthreads();
    }

    // ---- epilogue: bias + relu + fp32 store (+ bf16 shadow) ----
    #pragma unroll
    for (int nt = 0; nt < NT; nt++) {
        int col = wn * (FOUT / 4) + nt * 8 + tg * 2;
        float bx = __ldg(bias + col), by = __ldg(bias + col + 1);
        #pragma unroll
        for (int mt = 0; mt < 2; mt++) {
            #pragma unroll
            for (int hrow = 0; hrow < 2; hrow++) {
                int node = node_base + wm * 32 + mt * 16 + g + hrow * 8;
                if (node >= N) continue;
                float ox = c[mt][nt][hrow * 2 + 0] + bx;
                float oy = c[mt][nt][hrow * 2 + 1] + by;
                if (RELU) { ox = fmaxf(ox, 0.f); oy = fmaxf(oy, 0.f); }
                *(float2*)(of + node * FOUT + col) = make_float2(ox, oy);
                if (SHADOW != 0) {
                    __nv_bfloat162 p = __float22bfloat162_rn(make_float2(ox, oy));
                    *(__nv_bfloat162*)(sh + node * 128 + col) = p;
                }
            }
        }
    }
}

// ---------------- launcher ----------------------------------------------------
extern "C" void kernel_launch(void* const* d_in, const int* in_sizes, int n_in,
                              void* d_out, int out_size) {
    const float* feat = (const float*)d_in[0];
    const int*   src  = (const int*)d_in[1];
    const int*   dst  = (const int*)d_in[2];
    const float* W0   = (const float*)d_in[3];
    const float* b0   = (const float*)d_in[4];
    const float* W1   = (const float*)d_in[5];
    const float* b1   = (const float*)d_in[6];
    const float* W2   = (const float*)d_in[7];
    const float* b2   = (const float*)d_in[8];
    float* out = (float*)d_out;

    const int smem128 = (128 * (128 + 8) + 64 * 132) * 4;   // 103,424 B
    const int smem64  = (128 * ( 64 + 8) + 64 * 132) * 4;   //  70,656 B
    cudaFuncSetAttribute(gemm_k<128, true, 1>, cudaFuncAttributeMaxDynamicSharedMemorySize, smem128);
    cudaFuncSetAttribute(gemm_k<128, true, 2>, cudaFuncAttributeMaxDynamicSharedMemorySize, smem128);
    cudaFuncSetAttribute(gemm_k< 64, false, 0>, cudaFuncAttributeMaxDynamicSharedMemorySize, smem64);

    const int TB = 256;
    prep_all_k<<<(N * 64 + TB - 1) / TB, TB>>>(feat, W0, W1, W2);
    count_k<<<(E + TB - 1) / TB, TB>>>(dst);
    scanA_k<<<NBLK, SCAN_B>>>();
    scanB_k<<<1, 64>>>();
    scanC_k<<<NBLK, SCAN_B>>>();
    scatter_k<<<(E + TB - 1) / TB, TB>>>(src, dst);

    int ablocks = (N + 7) / 8;       // 6250 (1 node/warp)
    int gblocks = (N + 63) / 64;     // 782

    // layer 0: gather bf16 feat (g_bA) -> mean; self = fp32 feat; out g_h0 + shadow g_bB
    agg_k<<<ablocks, TB>>>(0);
    gemm_k<128, true, 1><<<gblocks, TB, smem128>>>(feat, 0, b0, nullptr, 1, 0);
    // layer 1: gather g_bB -> mean; self = g_h0; out g_h1 + shadow g_bA
    agg_k<<<ablocks, TB>>>(1);
    gemm_k<128, true, 2><<<gblocks, TB, smem128>>>(nullptr, 1, b1, nullptr, 2, 1);
    // layer 2: gather g_bA -> mean; self = g_h1; out = dout
    agg_k<<<ablocks, TB>>>(0);
    gemm_k< 64, false, 0><<<gblocks, TB, smem64>>>(nullptr, 2, b2, out, 0, 2);
}